// round 1
// baseline (speedup 1.0000x reference)
#include <cuda_runtime.h>

// ============================================================================
// BarrierNet fused kernel (fp32, round 1)
//  x[B,8] --(affine)--> x0
//  hid  = relu(x0 @ W1^T + b1)                [B,256]
//  h21  = relu(hid @ W21^T + b21); x31 = h21 @ W31^T + b31   [B,2]  (QP p)
//  h22  = relu(hid @ W22^T + b22); x32 = 4*sigmoid(h22 @ W32^T + b32) [B,2]
//  z    = argmin 0.5|z|^2 + p.z  s.t. G z <= h  (9 constraints, closed form)
// ============================================================================

#define TB        64      // rows per CTA
#define RPAD      68      // hid row stride (64 + 4 pad), 16B-aligned
#define CPAD      132     // W chunk col stride (128 + 4 pad), 16B-aligned
#define NTHREADS  256
#define REDS      65      // reduction buffer stride (conflict-free)

__constant__ float OBX[8] = {
    10.0f, 7.0710678118654755f, 6.123233995736766e-16f, -7.0710678118654755f,
    -10.0f, -7.0710678118654755f, -1.8369701987210297e-15f, 7.0710678118654755f };
__constant__ float OBY[8] = {
    0.0f, 7.0710678118654755f, 10.0f, 7.0710678118654755f,
    1.2246467991473532e-15f, -7.0710678118654755f, -10.0f, -7.0710678118654755f };

struct SmemLayout {
    float hid[256 * RPAD];   // 69632 B : hid[k][r], k-major
    float wch[32 * CPAD];    // 16896 B : W2 chunk wch[k][c]; reused as reduction buf
    float xs[TB * 8];        //  2048 B : x0 (pre-scaled features)
    float w31[2 * 128];      //  1024 B
    float w32[2 * 128];      //  1024 B
    float b21s[128];         //   512 B
    float b22s[128];         //   512 B
    float2 ps[TB];           //   512 B : x31 (QP p)
    float2 ss[TB];           //   512 B : x32 pre-sigmoid
};                           // ~92.7 KB total -> 2 CTAs/SM

__device__ __forceinline__ float4 ld4(const float* p) {
    return *reinterpret_cast<const float4*>(p);
}

extern "C" __global__ void __launch_bounds__(NTHREADS, 2)
barriernet_kernel(const float* __restrict__ x,   const float* __restrict__ meanv,
                  const float* __restrict__ stdv,
                  const float* __restrict__ W1,  const float* __restrict__ b1,
                  const float* __restrict__ W21, const float* __restrict__ b21,
                  const float* __restrict__ W31, const float* __restrict__ b31,
                  const float* __restrict__ W22, const float* __restrict__ b22,
                  const float* __restrict__ W32, const float* __restrict__ b32,
                  float* __restrict__ out, int Btot)
{
    extern __shared__ float smem_raw[];
    SmemLayout* S = reinterpret_cast<SmemLayout*>(smem_raw);
    const int tid  = threadIdx.x;
    const int row0 = blockIdx.x * TB;

    // ---- preload small tensors ------------------------------------------
    if (tid < 128) { S->b21s[tid] = b21[tid]; S->b22s[tid] = b22[tid]; }
    S->w31[tid] = W31[tid];          // 256 elems, 256 threads
    S->w32[tid] = W32[tid];
    for (int i = tid; i < TB * 8; i += NTHREADS) {
        int r = i >> 3, j = i & 7;
        int gr = row0 + r;
        float v = (gr < Btot) ? x[gr * 8 + j] : 0.0f;
        S->xs[i] = v * stdv[j] + meanv[j];
    }
    __syncthreads();

    // ---- phase 1: hid[k][r] = relu(b1[k] + sum_j x0[r][j]*W1[k][j]) ------
    {
        const int t = tid;               // hidden unit 0..255
        float w[8];
        #pragma unroll
        for (int j = 0; j < 8; j++) w[j] = W1[t * 8 + j];
        const float bb = b1[t];
        for (int r = 0; r < TB; r++) {
            float a = bb;
            #pragma unroll
            for (int j = 0; j < 8; j++) a = fmaf(S->xs[r * 8 + j], w[j], a);
            S->hid[t * RPAD + r] = fmaxf(a, 0.0f);
        }
    }

    // ---- phase 2: two GEMM branches --------------------------------------
    const int tx = tid & 15;             // 16 col-groups of 8
    const int ty = tid >> 4;             // 16 row-groups of 4
    const int rr = ty * 4;
    const int cc = tx * 8;

    for (int br = 0; br < 2; br++) {
        const float* __restrict__ W2  = br ? W22 : W21;
        const float* __restrict__ bsm = br ? S->b22s : S->b21s;
        float acc[4][8];
        #pragma unroll
        for (int i = 0; i < 4; i++)
            #pragma unroll
            for (int j = 0; j < 8; j++) acc[i][j] = 0.0f;

        for (int kk = 0; kk < 256; kk += 32) {
            __syncthreads();   // previous chunk (or reduction buffer) consumed
            #pragma unroll 4
            for (int idx = tid; idx < 128 * 32; idx += NTHREADS) {
                int k = idx & 31, c = idx >> 5;
                S->wch[k * CPAD + c] = W2[c * 256 + kk + k];
            }
            __syncthreads();
            #pragma unroll 8
            for (int k = 0; k < 32; k++) {
                float4 a0  = ld4(&S->hid[(kk + k) * RPAD + rr]);
                float4 b0  = ld4(&S->wch[k * CPAD + cc]);
                float4 b1v = ld4(&S->wch[k * CPAD + cc + 4]);
                float a[4] = { a0.x, a0.y, a0.z, a0.w };
                float b[8] = { b0.x, b0.y, b0.z, b0.w, b1v.x, b1v.y, b1v.z, b1v.w };
                #pragma unroll
                for (int i = 0; i < 4; i++)
                    #pragma unroll
                    for (int j = 0; j < 8; j++)
                        acc[i][j] = fmaf(a[i], b[j], acc[i][j]);
            }
        }

        // epilogue: relu(h + b2) then project with W3 (2x128); deterministic
        // smem reduction over the 16 tx groups (no float atomics).
        __syncthreads();                       // wch now free -> reduction buf
        const float* w3 = br ? S->w32 : S->w31;
        float* red0 = S->wch;                  // [16][REDS]
        float* red1 = S->wch + 16 * REDS;
        #pragma unroll
        for (int i = 0; i < 4; i++) {
            float p0 = 0.0f, p1 = 0.0f;
            #pragma unroll
            for (int j = 0; j < 8; j++) {
                float hv = fmaxf(acc[i][j] + bsm[cc + j], 0.0f);
                p0 = fmaf(hv, w3[cc + j],       p0);
                p1 = fmaf(hv, w3[128 + cc + j], p1);
            }
            red0[tx * REDS + rr + i] = p0;
            red1[tx * REDS + rr + i] = p1;
        }
        __syncthreads();
        if (tid < TB) {
            float p0 = 0.0f, p1 = 0.0f;
            #pragma unroll
            for (int g = 0; g < 16; g++) {     // fixed order -> deterministic
                p0 += red0[g * REDS + tid];
                p1 += red1[g * REDS + tid];
            }
            if (br == 0) S->ps[tid] = make_float2(p0 + b31[0], p1 + b31[1]);
            else         S->ss[tid] = make_float2(p0 + b32[0], p1 + b32[1]);
        }
    }
    __syncthreads();

    // ---- phase 3: closed-form 2D QP per row ------------------------------
    if (tid < TB) {
        const int gr = row0 + tid;
        if (gr < Btot) {
            const float* f = &S->xs[tid * 8];
            float px = f[0], py = f[1], th = f[2], v  = f[3];
            float ox = f[4], oy = f[5], ot = f[6], ov = f[7];
            float st = sinf(th), ct = cosf(th);
            float vs = v * st,  vc = v * ct;
            float s0 = 4.0f / (1.0f + expf(-S->ss[tid].x));
            float s1 = 4.0f / (1.0f + expf(-S->ss[tid].y));
            float ssum = s0 + s1, sprod = s0 * s1;

            float G0[9], G1[9], h[9];
            const float R  = 0.2f + 0.5f + 0.1f;
            const float R2 = R * R;
            #pragma unroll
            for (int i = 0; i < 8; i++) {
                float dx = px - OBX[i], dy = py - OBY[i];
                float bar  = dx * dx + dy * dy - R2;
                float bdot = 2.0f * dx * vc + 2.0f * dy * vs;
                float u1 = -2.0f * dx * vs + 2.0f * dy * vc;
                float u2 =  2.0f * dx * ct + 2.0f * dy * st;
                G0[i] = -u1; G1[i] = -u2;
                h[i] = 2.0f * v * v + ssum * bdot + sprod * bar;
            }
            {   // opponent constraint
                float dxo = px - ox, dyo = py - oy;
                float so = sinf(ot), co = cosf(ot);
                float bar  = dxo * dxo + dyo * dyo - 0.25f;
                float bdot = 2.0f * dxo * (vc - ov * co) + 2.0f * dyo * (vs - ov * so);
                float Lf2  = 2.0f * (v * v + ov * ov + 2.0f * v * ov * cosf(th - ot));
                float u1 = -2.0f * dxo * vs + 2.0f * dyo * vc;
                float u2 =  2.0f * dxo * ct + 2.0f * dyo * st;
                G0[8] = -u1; G1[8] = -u2;
                h[8] = Lf2 + ssum * bdot + sprod * bar;
            }
            float tol[9];
            #pragma unroll
            for (int i = 0; i < 9; i++) tol[i] = h[i] + 1e-6f * (1.0f + fabsf(h[i]));

            const float p0 = S->ps[tid].x, p1 = S->ps[tid].y;
            float bz0 = -p0, bz1 = -p1;          // argmin(all-inf) == index 0 == z0
            float bobj = 3.402823466e+38f;

            auto consider = [&](float zx, float zy) {
                bool feas = true;
                #pragma unroll
                for (int k = 0; k < 9; k++)
                    feas = feas && (zx * G0[k] + zy * G1[k] <= tol[k]);
                float obj = 0.5f * (zx * zx + zy * zy) + zx * p0 + zy * p1;
                if (feas && obj < bobj) { bobj = obj; bz0 = zx; bz1 = zy; }
            };

            consider(-p0, -p1);                              // active set {}
            #pragma unroll
            for (int i = 0; i < 9; i++) {                    // active set {i}
                float gg  = G0[i] * G0[i] + G1[i] * G1[i];
                float lam = (-(G0[i] * p0 + G1[i] * p1) - h[i]) / (gg + 1e-12f);
                if (lam >= -1e-8f)
                    consider(-p0 - lam * G0[i], -p1 - lam * G1[i]);
            }
            for (int i = 0; i < 8; i++) {                    // active set {i,j}, triu order
                for (int j = i + 1; j < 9; j++) {
                    float det = G0[i] * G1[j] - G1[i] * G0[j];
                    if (fabsf(det) > 1e-9f) {
                        float zx = (h[i] * G1[j] - h[j] * G1[i]) / det;
                        float zy = (G0[i] * h[j] - G0[j] * h[i]) / det;
                        float r0 = -(zx + p0), r1 = -(zy + p1);
                        float li = (G1[j] * r0 - G0[j] * r1) / det;
                        float lj = (G0[i] * r1 - G1[i] * r0) / det;
                        if (li >= -1e-8f && lj >= -1e-8f) consider(zx, zy);
                    }
                }
            }
            out[gr * 2 + 0] = bz0;
            out[gr * 2 + 1] = bz1;
        }
    }
}

extern "C" void kernel_launch(void* const* d_in, const int* in_sizes, int n_in,
                              void* d_out, int out_size)
{
    const float* x     = (const float*)d_in[0];
    const float* meanv = (const float*)d_in[1];
    const float* stdv  = (const float*)d_in[2];
    const float* W1    = (const float*)d_in[3];
    const float* b1    = (const float*)d_in[4];
    const float* W21   = (const float*)d_in[5];
    const float* b21   = (const float*)d_in[6];
    const float* W31   = (const float*)d_in[7];
    const float* b31   = (const float*)d_in[8];
    const float* W22   = (const float*)d_in[9];
    const float* b22   = (const float*)d_in[10];
    const float* W32   = (const float*)d_in[11];
    const float* b32   = (const float*)d_in[12];
    float* out = (float*)d_out;

    const int Btot = in_sizes[0] / 8;
    const int grid = (Btot + TB - 1) / TB;
    const size_t smem = sizeof(SmemLayout);

    cudaFuncSetAttribute(barriernet_kernel,
                         cudaFuncAttributeMaxDynamicSharedMemorySize, (int)smem);
    barriernet_kernel<<<grid, NTHREADS, smem>>>(
        x, meanv, stdv, W1, b1, W21, b21, W31, b31, W22, b22, W32, b32,
        out, Btot);
}

// round 3
// speedup vs baseline: 3.0039x; 3.0039x over previous
#include <cuda_runtime.h>
#include <cuda_bf16.h>
#include <cstdint>

// ============================================================================
// BarrierNet — warp-level HMMA (bf16 hi/lo split ~ fp32) + fused epilogue + QP
// (tcgen05 PTX rejected by this harness's ptxas target; mma.sync works)
// ============================================================================

#define NTH        512
#define KSTR       72            // padded k-stride (bf16 elems) = 144 B
#define KSTRB      144

// smem byte offsets
#define A_HI_OFF   0             // 128 x 72 bf16 = 18432
#define A_LO_OFF   18432
#define B_HI_OFF   36864         // 256 x 72 bf16 = 36864
#define B_LO_OFF   73728
#define XS_OFF     110592        // 128*8 f32 = 4096
#define B2_OFF     114688        // 256 f32
#define W3A_OFF    115712        // 256 f32
#define W3B_OFF    116736        // 256 f32
#define RED_OFF    117760        // 4 x 128 float2 = 4096
#define SMEM_TOTAL 121856

// prep image: [chunk4][plane2(hi,lo)][nc256][72] bf16
__device__ __align__(16) unsigned char BIMG[294912];

__constant__ float OBX[8] = {
    10.0f, 7.0710678118654755f, 6.123233995736766e-16f, -7.0710678118654755f,
    -10.0f, -7.0710678118654755f, -1.8369701987210297e-15f, 7.0710678118654755f };
__constant__ float OBY[8] = {
    0.0f, 7.0710678118654755f, 10.0f, 7.0710678118654755f,
    1.2246467991473532e-15f, -7.0710678118654755f, -10.0f, -7.0710678118654755f };

__device__ __forceinline__ void mma16816(float* d, const uint32_t* a,
                                         uint32_t b0, uint32_t b1) {
    asm volatile(
        "mma.sync.aligned.m16n8k16.row.col.f32.bf16.bf16.f32 "
        "{%0,%1,%2,%3}, {%4,%5,%6,%7}, {%8,%9}, {%0,%1,%2,%3};"
        : "+f"(d[0]), "+f"(d[1]), "+f"(d[2]), "+f"(d[3])
        : "r"(a[0]), "r"(a[1]), "r"(a[2]), "r"(a[3]), "r"(b0), "r"(b1));
}

// ------------------------------------------------------------ QP (round-1)
__device__ __forceinline__ float2 qp_solve(const float* f, float p0, float p1,
                                           float s0, float s1) {
    float px = f[0], py = f[1], th = f[2], v  = f[3];
    float ox = f[4], oy = f[5], ot = f[6], ov = f[7];
    float st = sinf(th), ct = cosf(th);
    float vs = v * st,  vc = v * ct;
    float ssum = s0 + s1, sprod = s0 * s1;

    float G0[9], G1[9], h[9];
    const float R2 = 0.8f * 0.8f;
    #pragma unroll
    for (int i = 0; i < 8; i++) {
        float dx = px - OBX[i], dy = py - OBY[i];
        float bar  = dx * dx + dy * dy - R2;
        float bdot = 2.0f * dx * vc + 2.0f * dy * vs;
        G0[i] = -(-2.0f * dx * vs + 2.0f * dy * vc);
        G1[i] = -( 2.0f * dx * ct + 2.0f * dy * st);
        h[i]  = 2.0f * v * v + ssum * bdot + sprod * bar;
    }
    {
        float dxo = px - ox, dyo = py - oy;
        float so = sinf(ot), co = cosf(ot);
        float bar  = dxo * dxo + dyo * dyo - 0.25f;
        float bdot = 2.0f * dxo * (vc - ov * co) + 2.0f * dyo * (vs - ov * so);
        float Lf2  = 2.0f * (v * v + ov * ov + 2.0f * v * ov * cosf(th - ot));
        G0[8] = -(-2.0f * dxo * vs + 2.0f * dyo * vc);
        G1[8] = -( 2.0f * dxo * ct + 2.0f * dyo * st);
        h[8]  = Lf2 + ssum * bdot + sprod * bar;
    }
    float tol[9];
    #pragma unroll
    for (int i = 0; i < 9; i++) tol[i] = h[i] + 1e-6f * (1.0f + fabsf(h[i]));

    float bz0 = -p0, bz1 = -p1;
    float bobj = 3.402823466e+38f;
    auto consider = [&](float zx, float zy) {
        bool feas = true;
        #pragma unroll
        for (int k = 0; k < 9; k++)
            feas = feas && (zx * G0[k] + zy * G1[k] <= tol[k]);
        float obj = 0.5f * (zx * zx + zy * zy) + zx * p0 + zy * p1;
        if (feas && obj < bobj) { bobj = obj; bz0 = zx; bz1 = zy; }
    };
    consider(-p0, -p1);
    #pragma unroll
    for (int i = 0; i < 9; i++) {
        float gg  = G0[i] * G0[i] + G1[i] * G1[i];
        float lam = (-(G0[i] * p0 + G1[i] * p1) - h[i]) / (gg + 1e-12f);
        if (lam >= -1e-8f) consider(-p0 - lam * G0[i], -p1 - lam * G1[i]);
    }
    for (int i = 0; i < 8; i++) {
        for (int j = i + 1; j < 9; j++) {
            float det = G0[i] * G1[j] - G1[i] * G0[j];
            if (fabsf(det) > 1e-9f) {
                float zx = (h[i] * G1[j] - h[j] * G1[i]) / det;
                float zy = (G0[i] * h[j] - G0[j] * h[i]) / det;
                float r0 = -(zx + p0), r1 = -(zy + p1);
                float li = (G1[j] * r0 - G0[j] * r1) / det;
                float lj = (G0[i] * r1 - G1[i] * r0) / det;
                if (li >= -1e-8f && lj >= -1e-8f) consider(zx, zy);
            }
        }
    }
    return make_float2(bz0, bz1);
}

// ------------------------------------------- prep: W21/W22 -> bf16 hi/lo image
extern "C" __global__ void bnet_prep(const float* __restrict__ W21,
                                     const float* __restrict__ W22) {
    int idx = blockIdx.x * 256 + threadIdx.x;   // 65536 = 2br * 128n * 256k
    int br = idx >> 15;
    int n  = (idx >> 8) & 127;
    int k  = idx & 255;
    const float* W = br ? W22 : W21;
    float v = W[n * 256 + k];
    __nv_bfloat16 hi = __float2bfloat16(v);
    __nv_bfloat16 lo = __float2bfloat16(v - __bfloat162float(hi));
    int c  = k >> 6;
    int kk = k & 63;
    int nc = br * 128 + n;
    size_t base = ((size_t)c * 2 * 256 + nc) * KSTRB + kk * 2;
    *(__nv_bfloat16*)(BIMG + base)                         = hi;   // hi plane
    *(__nv_bfloat16*)(BIMG + base + (size_t)256 * KSTRB)   = lo;   // lo plane
}

// ------------------------------------------------------------- main kernel
extern "C" __global__ void __launch_bounds__(NTH, 1)
bnet_main(const float* __restrict__ x,   const float* __restrict__ meanv,
          const float* __restrict__ stdv,
          const float* __restrict__ W1,  const float* __restrict__ b1,
          const float* __restrict__ b21v, const float* __restrict__ W31,
          const float* __restrict__ b31v,
          const float* __restrict__ b22v, const float* __restrict__ W32,
          const float* __restrict__ b32v,
          float* __restrict__ out, int Btot)
{
    extern __shared__ unsigned char sm[];
    const int tid  = threadIdx.x;
    const int wp   = tid >> 5;
    const int lane = tid & 31;
    const int g    = lane >> 2;        // group id (0..7)
    const int t    = lane & 3;         // thread-in-group
    const int rg   = wp & 3;           // warp row group: rows rg*32..+32
    const int cg   = wp >> 2;          // warp col group: cols cg*64..+64 of 256
    const int row0 = blockIdx.x * 128;

    float* xs   = (float*)(sm + XS_OFF);
    float* b2s  = (float*)(sm + B2_OFF);
    float* w3a  = (float*)(sm + W3A_OFF);
    float* w3b  = (float*)(sm + W3B_OFF);
    float2* red = (float2*)(sm + RED_OFF);

    // ---- preload small tensors ------------------------------------------
    if (tid < 256) {
        b2s[tid] = (tid < 128) ? b21v[tid] : b22v[tid - 128];
        w3a[tid] = (tid < 128) ? W31[tid] : W32[tid - 128];
        w3b[tid] = (tid < 128) ? W31[128 + tid] : W32[tid];  // row 1
    }
    for (int i = tid; i < 128 * 8; i += NTH) {
        int r = i >> 3, j = i & 7;
        int gr = row0 + r;
        float v = (gr < Btot) ? x[gr * 8 + j] : 0.0f;
        xs[i] = v * stdv[j] + meanv[j];
    }

    float acc[2][8][4];
    #pragma unroll
    for (int mt = 0; mt < 2; mt++)
        #pragma unroll
        for (int nt = 0; nt < 8; nt++)
            #pragma unroll
            for (int e = 0; e < 4; e++) acc[mt][nt][e] = 0.0f;

    const int u   = tid & 63;          // hidden unit within chunk
    const int rg8 = tid >> 6;          // phase-1 row group (16 rows)

    __syncthreads();

    for (int c = 0; c < 4; c++) {
        if (c > 0) __syncthreads();    // smem consumed by previous chunk

        // phase 1: hid chunk (64 units) -> A hi/lo
        {
            int ug = c * 64 + u;
            const float4* w4 = (const float4*)(W1 + ug * 8);
            float4 wa = w4[0], wb = w4[1];
            float bb = b1[ug];
            #pragma unroll 4
            for (int i = 0; i < 16; i++) {
                int m = rg8 * 16 + i;
                float4 fa = *(const float4*)(xs + m * 8);
                float4 fb = *(const float4*)(xs + m * 8 + 4);
                float a = bb;
                a = fmaf(fa.x, wa.x, a); a = fmaf(fa.y, wa.y, a);
                a = fmaf(fa.z, wa.z, a); a = fmaf(fa.w, wa.w, a);
                a = fmaf(fb.x, wb.x, a); a = fmaf(fb.y, wb.y, a);
                a = fmaf(fb.z, wb.z, a); a = fmaf(fb.w, wb.w, a);
                a = fmaxf(a, 0.0f);
                __nv_bfloat16 hi = __float2bfloat16(a);
                __nv_bfloat16 lo = __float2bfloat16(a - __bfloat162float(hi));
                *(__nv_bfloat16*)(sm + A_HI_OFF + m * KSTRB + u * 2) = hi;
                *(__nv_bfloat16*)(sm + A_LO_OFF + m * KSTRB + u * 2) = lo;
            }
        }
        // B chunk copy: hi+lo planes contiguous, 73728 B
        {
            const uint4* src = (const uint4*)(BIMG + (size_t)c * 73728);
            uint4* dst = (uint4*)(sm + B_HI_OFF);
            #pragma unroll
            for (int it = 0; it < 9; it++)
                dst[it * NTH + tid] = src[it * NTH + tid];
        }
        __syncthreads();

        // mainloop: 4 k-steps of 16
        const unsigned char* Ah = sm + A_HI_OFF + (rg * 32 + g) * KSTRB + t * 4;
        const unsigned char* Bh = sm + B_HI_OFF + (cg * 64 + g) * KSTRB + t * 4;
        #pragma unroll
        for (int k0 = 0; k0 < 64; k0 += 16) {
            uint32_t ah[2][4], al[2][4];
            #pragma unroll
            for (int mt = 0; mt < 2; mt++) {
                const unsigned char* p = Ah + mt * 16 * KSTRB + k0 * 2;
                ah[mt][0] = *(const uint32_t*)(p);
                ah[mt][1] = *(const uint32_t*)(p + 8 * KSTRB);
                ah[mt][2] = *(const uint32_t*)(p + 16);
                ah[mt][3] = *(const uint32_t*)(p + 8 * KSTRB + 16);
                const unsigned char* q = p + (A_LO_OFF - A_HI_OFF);
                al[mt][0] = *(const uint32_t*)(q);
                al[mt][1] = *(const uint32_t*)(q + 8 * KSTRB);
                al[mt][2] = *(const uint32_t*)(q + 16);
                al[mt][3] = *(const uint32_t*)(q + 8 * KSTRB + 16);
            }
            #pragma unroll
            for (int nt = 0; nt < 8; nt++) {
                const unsigned char* p = Bh + nt * 8 * KSTRB + k0 * 2;
                uint32_t bh0 = *(const uint32_t*)(p);
                uint32_t bh1 = *(const uint32_t*)(p + 16);
                const unsigned char* q = p + (B_LO_OFF - B_HI_OFF);
                uint32_t bl0 = *(const uint32_t*)(q);
                uint32_t bl1 = *(const uint32_t*)(q + 16);
                #pragma unroll
                for (int mt = 0; mt < 2; mt++) {
                    mma16816(acc[mt][nt], ah[mt], bh0, bh1);
                    mma16816(acc[mt][nt], al[mt], bh0, bh1);
                    mma16816(acc[mt][nt], ah[mt], bl0, bl1);
                }
            }
        }
    }
    __syncthreads();

    // ---- epilogue: relu+bias, project to 2 outs, reduce -------------------
    {
        const int branch  = cg >> 1;            // 0: x31 path, 1: x32 path
        const int colbase = branch * 128 + (cg & 1) * 64;
        float y0A[2] = {0, 0}, y1A[2] = {0, 0};  // [mt]
        float y0B[2] = {0, 0}, y1B[2] = {0, 0};
        #pragma unroll
        for (int mt = 0; mt < 2; mt++) {
            #pragma unroll
            for (int nt = 0; nt < 8; nt++) {
                int c0 = colbase + nt * 8 + t * 2;
                float w3a0 = w3a[c0], w3a1 = w3a[c0 + 1];
                float w3b0 = w3b[c0], w3b1 = w3b[c0 + 1];
                float bb0 = b2s[c0], bb1 = b2s[c0 + 1];
                float h0 = fmaxf(acc[mt][nt][0] + bb0, 0.0f);
                float h1 = fmaxf(acc[mt][nt][1] + bb1, 0.0f);
                float h2 = fmaxf(acc[mt][nt][2] + bb0, 0.0f);
                float h3 = fmaxf(acc[mt][nt][3] + bb1, 0.0f);
                y0A[mt] = fmaf(h0, w3a0, fmaf(h1, w3a1, y0A[mt]));
                y1A[mt] = fmaf(h0, w3b0, fmaf(h1, w3b1, y1A[mt]));
                y0B[mt] = fmaf(h2, w3a0, fmaf(h3, w3a1, y0B[mt]));
                y1B[mt] = fmaf(h2, w3b0, fmaf(h3, w3b1, y1B[mt]));
            }
        }
        #pragma unroll
        for (int mt = 0; mt < 2; mt++) {
            #pragma unroll
            for (int msk = 1; msk <= 2; msk <<= 1) {
                y0A[mt] += __shfl_xor_sync(0xFFFFFFFFu, y0A[mt], msk);
                y1A[mt] += __shfl_xor_sync(0xFFFFFFFFu, y1A[mt], msk);
                y0B[mt] += __shfl_xor_sync(0xFFFFFFFFu, y0B[mt], msk);
                y1B[mt] += __shfl_xor_sync(0xFFFFFFFFu, y1B[mt], msk);
            }
        }
        if (t == 0) {
            #pragma unroll
            for (int mt = 0; mt < 2; mt++) {
                int rA = rg * 32 + mt * 16 + g;
                red[cg * 128 + rA]     = make_float2(y0A[mt], y1A[mt]);
                red[cg * 128 + rA + 8] = make_float2(y0B[mt], y1B[mt]);
            }
        }
    }
    __syncthreads();

    if (tid < 128) {
        const int gr = row0 + tid;
        if (gr < Btot) {
            float2 a0 = red[tid],       a1 = red[128 + tid];
            float2 c0 = red[256 + tid], c1 = red[384 + tid];
            float p0 = a0.x + a1.x + b31v[0];
            float p1 = a0.y + a1.y + b31v[1];
            float q0 = c0.x + c1.x + b32v[0];
            float q1 = c0.y + c1.y + b32v[1];
            float s0 = 4.0f / (1.0f + expf(-q0));
            float s1 = 4.0f / (1.0f + expf(-q1));
            float2 z = qp_solve(&xs[tid * 8], p0, p1, s0, s1);
            *(float2*)(out + gr * 2) = z;
        }
    }
}

// ---------------------------------------------------------------- launcher
extern "C" void kernel_launch(void* const* d_in, const int* in_sizes, int n_in,
                              void* d_out, int out_size)
{
    const float* x     = (const float*)d_in[0];
    const float* meanv = (const float*)d_in[1];
    const float* stdv  = (const float*)d_in[2];
    const float* W1    = (const float*)d_in[3];
    const float* b1    = (const float*)d_in[4];
    const float* W21   = (const float*)d_in[5];
    const float* b21   = (const float*)d_in[6];
    const float* W31   = (const float*)d_in[7];
    const float* b31   = (const float*)d_in[8];
    const float* W22   = (const float*)d_in[9];
    const float* b22   = (const float*)d_in[10];
    const float* W32   = (const float*)d_in[11];
    const float* b32   = (const float*)d_in[12];
    float* out = (float*)d_out;

    const int Btot = in_sizes[0] / 8;
    const int grid = (Btot + 127) / 128;

    bnet_prep<<<256, 256>>>(W21, W22);

    cudaFuncSetAttribute(bnet_main, cudaFuncAttributeMaxDynamicSharedMemorySize,
                         SMEM_TOTAL);
    bnet_main<<<grid, NTH, SMEM_TOTAL>>>(x, meanv, stdv, W1, b1,
                                         b21, W31, b31, b22, W32, b32,
                                         out, Btot);
}

// round 4
// speedup vs baseline: 3.1876x; 1.0611x over previous
#include <cuda_runtime.h>
#include <cuda_bf16.h>
#include <cstdint>

// ============================================================================
// BarrierNet — HMMA bf16 hi/lo (~fp32) + ldmatrix + cp.async pipelined B
// ============================================================================

#define NTH        512
#define ASTR       528            // A row stride bytes (256*2 + 16 pad)
#define BSTR       144            // B row stride bytes (64*2 + 16 pad)

// smem byte offsets
#define A_HI_OFF   0              // 128 x 528            = 67584
#define A_LO_OFF   67584
#define B_HI_OFF   135168         // 256 x 144            = 36864
#define B_LO_OFF   172032
#define XS_OFF     208896         // 128*8 f32 = 4096
#define B2_OFF     212992         // 256 f32
#define W3A_OFF    214016
#define W3B_OFF    215040
#define RED_OFF    216064         // 4 x 128 float2 = 4096
#define SMEM_TOTAL 220160

// prep image: [chunk4][plane2(hi,lo)][nc256][72] bf16  (73728 B per chunk)
__device__ __align__(16) unsigned char BIMG[294912];

__constant__ float OBX[8] = {
    10.0f, 7.0710678118654755f, 6.123233995736766e-16f, -7.0710678118654755f,
    -10.0f, -7.0710678118654755f, -1.8369701987210297e-15f, 7.0710678118654755f };
__constant__ float OBY[8] = {
    0.0f, 7.0710678118654755f, 10.0f, 7.0710678118654755f,
    1.2246467991473532e-15f, -7.0710678118654755f, -10.0f, -7.0710678118654755f };

// ---------------------------------------------------------------- asm helpers
__device__ __forceinline__ uint32_t smem_u32(const void* p) {
    uint32_t a;
    asm("{ .reg .u64 t; cvta.to.shared.u64 t, %1; cvt.u32.u64 %0, t; }"
        : "=r"(a) : "l"(p));
    return a;
}
__device__ __forceinline__ void mma16816(float* d, const uint32_t* a,
                                         uint32_t b0, uint32_t b1) {
    asm volatile(
        "mma.sync.aligned.m16n8k16.row.col.f32.bf16.bf16.f32 "
        "{%0,%1,%2,%3}, {%4,%5,%6,%7}, {%8,%9}, {%0,%1,%2,%3};"
        : "+f"(d[0]), "+f"(d[1]), "+f"(d[2]), "+f"(d[3])
        : "r"(a[0]), "r"(a[1]), "r"(a[2]), "r"(a[3]), "r"(b0), "r"(b1));
}
__device__ __forceinline__ void ldsm4(uint32_t* r, uint32_t addr) {
    asm volatile("ldmatrix.sync.aligned.m8n8.x4.shared.b16 {%0,%1,%2,%3}, [%4];"
                 : "=r"(r[0]), "=r"(r[1]), "=r"(r[2]), "=r"(r[3]) : "r"(addr));
}
#define CPASYNC16(dst, src) \
    asm volatile("cp.async.cg.shared.global [%0], [%1], 16;" \
                 :: "r"(dst), "l"(src))
#define CPCOMMIT() asm volatile("cp.async.commit_group;")
#define CPWAIT0()  asm volatile("cp.async.wait_group 0;")
#define CPWAIT1()  asm volatile("cp.async.wait_group 1;")

// ------------------------------------------------------------ QP (validated)
__device__ __forceinline__ float2 qp_solve(const float* f, float p0, float p1,
                                           float s0, float s1) {
    float px = f[0], py = f[1], th = f[2], v  = f[3];
    float ox = f[4], oy = f[5], ot = f[6], ov = f[7];
    float st = sinf(th), ct = cosf(th);
    float vs = v * st,  vc = v * ct;
    float ssum = s0 + s1, sprod = s0 * s1;

    float G0[9], G1[9], h[9];
    const float R2 = 0.8f * 0.8f;
    #pragma unroll
    for (int i = 0; i < 8; i++) {
        float dx = px - OBX[i], dy = py - OBY[i];
        float bar  = dx * dx + dy * dy - R2;
        float bdot = 2.0f * dx * vc + 2.0f * dy * vs;
        G0[i] = -(-2.0f * dx * vs + 2.0f * dy * vc);
        G1[i] = -( 2.0f * dx * ct + 2.0f * dy * st);
        h[i]  = 2.0f * v * v + ssum * bdot + sprod * bar;
    }
    {
        float dxo = px - ox, dyo = py - oy;
        float so = sinf(ot), co = cosf(ot);
        float bar  = dxo * dxo + dyo * dyo - 0.25f;
        float bdot = 2.0f * dxo * (vc - ov * co) + 2.0f * dyo * (vs - ov * so);
        float Lf2  = 2.0f * (v * v + ov * ov + 2.0f * v * ov * cosf(th - ot));
        G0[8] = -(-2.0f * dxo * vs + 2.0f * dyo * vc);
        G1[8] = -( 2.0f * dxo * ct + 2.0f * dyo * st);
        h[8]  = Lf2 + ssum * bdot + sprod * bar;
    }
    float tol[9];
    #pragma unroll
    for (int i = 0; i < 9; i++) tol[i] = h[i] + 1e-6f * (1.0f + fabsf(h[i]));

    float bz0 = -p0, bz1 = -p1;
    float bobj = 3.402823466e+38f;
    auto consider = [&](float zx, float zy) {
        bool feas = true;
        #pragma unroll
        for (int k = 0; k < 9; k++)
            feas = feas && (zx * G0[k] + zy * G1[k] <= tol[k]);
        float obj = 0.5f * (zx * zx + zy * zy) + zx * p0 + zy * p1;
        if (feas && obj < bobj) { bobj = obj; bz0 = zx; bz1 = zy; }
    };
    consider(-p0, -p1);
    #pragma unroll
    for (int i = 0; i < 9; i++) {
        float gg  = G0[i] * G0[i] + G1[i] * G1[i];
        float lam = (-(G0[i] * p0 + G1[i] * p1) - h[i]) / (gg + 1e-12f);
        if (lam >= -1e-8f) consider(-p0 - lam * G0[i], -p1 - lam * G1[i]);
    }
    for (int i = 0; i < 8; i++) {
        for (int j = i + 1; j < 9; j++) {
            float det = G0[i] * G1[j] - G1[i] * G0[j];
            if (fabsf(det) > 1e-9f) {
                float zx = (h[i] * G1[j] - h[j] * G1[i]) / det;
                float zy = (G0[i] * h[j] - G0[j] * h[i]) / det;
                float r0 = -(zx + p0), r1 = -(zy + p1);
                float li = (G1[j] * r0 - G0[j] * r1) / det;
                float lj = (G0[i] * r1 - G1[i] * r0) / det;
                if (li >= -1e-8f && lj >= -1e-8f) consider(zx, zy);
            }
        }
    }
    return make_float2(bz0, bz1);
}

// ------------------------------------------- prep: W21/W22 -> bf16 hi/lo image
extern "C" __global__ void bnet_prep(const float* __restrict__ W21,
                                     const float* __restrict__ W22) {
    int idx = blockIdx.x * 256 + threadIdx.x;   // 65536 = 2br * 128n * 256k
    int br = idx >> 15;
    int n  = (idx >> 8) & 127;
    int k  = idx & 255;
    const float* W = br ? W22 : W21;
    float v = W[n * 256 + k];
    __nv_bfloat16 hi = __float2bfloat16(v);
    __nv_bfloat16 lo = __float2bfloat16(v - __bfloat162float(hi));
    int c  = k >> 6;
    int kk = k & 63;
    int nc = br * 128 + n;
    size_t base = ((size_t)c * 2 * 256 + nc) * BSTR + kk * 2;
    *(__nv_bfloat16*)(BIMG + base)                        = hi;
    *(__nv_bfloat16*)(BIMG + base + (size_t)256 * BSTR)   = lo;
}

// ------------------------------------------------------------- main kernel
extern "C" __global__ void __launch_bounds__(NTH, 1)
bnet_main(const float* __restrict__ x,   const float* __restrict__ meanv,
          const float* __restrict__ stdv,
          const float* __restrict__ W1,  const float* __restrict__ b1,
          const float* __restrict__ b21v, const float* __restrict__ W31,
          const float* __restrict__ b31v,
          const float* __restrict__ b22v, const float* __restrict__ W32,
          const float* __restrict__ b32v,
          float* __restrict__ out, int Btot)
{
    extern __shared__ unsigned char sm[];
    const uint32_t smb = smem_u32(sm);
    const int tid  = threadIdx.x;
    const int wp   = tid >> 5;
    const int lane = tid & 31;
    const int g    = lane >> 2;
    const int t    = lane & 3;
    const int rg   = wp & 3;           // rows rg*32..+32
    const int cg   = wp >> 2;          // cols cg*64..+64
    const int row0 = blockIdx.x * 128;

    float* xs   = (float*)(sm + XS_OFF);
    float* b2s  = (float*)(sm + B2_OFF);
    float* w3a  = (float*)(sm + W3A_OFF);
    float* w3b  = (float*)(sm + W3B_OFF);
    float2* red = (float2*)(sm + RED_OFF);

    // ---- B chunk-0 prefetch (cp.async) -----------------------------------
    const unsigned char* bimg = BIMG;
    auto fill_plane = [&](uint32_t dstoff, const unsigned char* src) {
        #pragma unroll
        for (int i = 0; i < 4; i++) {
            int idx = tid + i * NTH;
            CPASYNC16(smb + dstoff + idx * 16, src + idx * 16);
        }
        if (tid < 256) {
            int idx = 2048 + tid;
            CPASYNC16(smb + dstoff + idx * 16, src + idx * 16);
        }
    };
    fill_plane(B_HI_OFF, bimg + 0 * 73728);          CPCOMMIT();
    fill_plane(B_LO_OFF, bimg + 0 * 73728 + 36864);  CPCOMMIT();

    // ---- small tensors + x-scale ------------------------------------------
    if (tid < 256) {
        b2s[tid] = (tid < 128) ? b21v[tid] : b22v[tid - 128];
        w3a[tid] = (tid < 128) ? W31[tid] : W32[tid - 128];
        w3b[tid] = (tid < 128) ? W31[128 + tid] : W32[tid];
    }
    for (int i = tid; i < 128 * 8; i += NTH) {
        int r = i >> 3, j = i & 7;
        int gr = row0 + r;
        float v = (gr < Btot) ? x[gr * 8 + j] : 0.0f;
        xs[i] = v * stdv[j] + meanv[j];
    }
    __syncthreads();    // xs ready for phase 1

    // ---- phase 1: full hid (K=256) -> A hi/lo -----------------------------
    {
        const int up = tid & 127;       // unit pair: units 2up, 2up+1
        const int rq = tid >> 7;        // row quarter: rows rq*32..+32
        const float4* w4 = (const float4*)(W1 + up * 16);
        float4 w0a = w4[0], w0b = w4[1], w1a = w4[2], w1b = w4[3];
        float bb0 = b1[up * 2], bb1 = b1[up * 2 + 1];
        #pragma unroll 4
        for (int i = 0; i < 32; i++) {
            int m = rq * 32 + i;
            float4 fa = *(const float4*)(xs + m * 8);
            float4 fb = *(const float4*)(xs + m * 8 + 4);
            float a0 = bb0, a1 = bb1;
            a0 = fmaf(fa.x, w0a.x, a0); a0 = fmaf(fa.y, w0a.y, a0);
            a0 = fmaf(fa.z, w0a.z, a0); a0 = fmaf(fa.w, w0a.w, a0);
            a0 = fmaf(fb.x, w0b.x, a0); a0 = fmaf(fb.y, w0b.y, a0);
            a0 = fmaf(fb.z, w0b.z, a0); a0 = fmaf(fb.w, w0b.w, a0);
            a1 = fmaf(fa.x, w1a.x, a1); a1 = fmaf(fa.y, w1a.y, a1);
            a1 = fmaf(fa.z, w1a.z, a1); a1 = fmaf(fa.w, w1a.w, a1);
            a1 = fmaf(fb.x, w1b.x, a1); a1 = fmaf(fb.y, w1b.y, a1);
            a1 = fmaf(fb.z, w1b.z, a1); a1 = fmaf(fb.w, w1b.w, a1);
            a0 = fmaxf(a0, 0.0f); a1 = fmaxf(a1, 0.0f);
            __nv_bfloat16 h0 = __float2bfloat16(a0);
            __nv_bfloat16 h1 = __float2bfloat16(a1);
            float l0f = a0 - __bfloat162float(h0);
            float l1f = a1 - __bfloat162float(h1);
            __nv_bfloat16 l0 = __float2bfloat16(l0f);
            __nv_bfloat16 l1 = __float2bfloat16(l1f);
            uint32_t hw = ((uint32_t)*(uint16_t*)&h1 << 16) | *(uint16_t*)&h0;
            uint32_t lw = ((uint32_t)*(uint16_t*)&l1 << 16) | *(uint16_t*)&l0;
            *(uint32_t*)(sm + A_HI_OFF + m * ASTR + up * 4) = hw;
            *(uint32_t*)(sm + A_LO_OFF + m * ASTR + up * 4) = lw;
        }
    }
    CPWAIT0();          // B chunk 0 (hi+lo) arrived
    __syncthreads();    // A image + B visible to all

    // ---- mainloop ----------------------------------------------------------
    float acc[2][8][4];
    #pragma unroll
    for (int mt = 0; mt < 2; mt++)
        #pragma unroll
        for (int nt = 0; nt < 8; nt++)
            #pragma unroll
            for (int e = 0; e < 4; e++) acc[mt][nt][e] = 0.0f;

    // ldmatrix base addresses
    const uint32_t aBase = smb + A_HI_OFF
        + (rg * 32 + ((lane >> 3) & 1) * 8 + (lane & 7)) * ASTR
        + (lane >> 4) * 16;
    const uint32_t bBase = smb + B_HI_OFF
        + (cg * 64 + ((lane >> 4) & 1) * 8 + (lane & 7)) * BSTR
        + ((lane >> 3) & 1) * 16;

    for (int c = 0; c < 4; c++) {
        const uint32_t ak = aBase + c * 128;   // c*64 k-elems * 2B

        // --- hi-B terms: Ahi*Bhi + Alo*Bhi ---
        #pragma unroll
        for (int k0 = 0; k0 < 64; k0 += 16) {
            uint32_t ah[2][4], al[2][4], bb[4][4];
            #pragma unroll
            for (int mt = 0; mt < 2; mt++) {
                ldsm4(ah[mt], ak + mt * (16 * ASTR) + k0 * 2);
                ldsm4(al[mt], ak + mt * (16 * ASTR) + k0 * 2 + (A_LO_OFF - A_HI_OFF));
            }
            #pragma unroll
            for (int pr = 0; pr < 4; pr++)
                ldsm4(bb[pr], bBase + pr * (16 * BSTR) + k0 * 2);
            #pragma unroll
            for (int pr = 0; pr < 4; pr++) {
                #pragma unroll
                for (int mt = 0; mt < 2; mt++) {
                    mma16816(acc[mt][2 * pr],     ah[mt], bb[pr][0], bb[pr][1]);
                    mma16816(acc[mt][2 * pr],     al[mt], bb[pr][0], bb[pr][1]);
                    mma16816(acc[mt][2 * pr + 1], ah[mt], bb[pr][2], bb[pr][3]);
                    mma16816(acc[mt][2 * pr + 1], al[mt], bb[pr][2], bb[pr][3]);
                }
            }
        }
        __syncthreads();                              // BHI(c) consumed
        if (c < 3) { fill_plane(B_HI_OFF, bimg + (c + 1) * 73728); CPCOMMIT(); }

        // --- lo-B term: Ahi*Blo ---
        #pragma unroll
        for (int k0 = 0; k0 < 64; k0 += 16) {
            uint32_t ah[2][4], bb[4][4];
            #pragma unroll
            for (int mt = 0; mt < 2; mt++)
                ldsm4(ah[mt], ak + mt * (16 * ASTR) + k0 * 2);
            #pragma unroll
            for (int pr = 0; pr < 4; pr++)
                ldsm4(bb[pr], bBase + pr * (16 * BSTR) + k0 * 2 + (B_LO_OFF - B_HI_OFF));
            #pragma unroll
            for (int pr = 0; pr < 4; pr++) {
                #pragma unroll
                for (int mt = 0; mt < 2; mt++) {
                    mma16816(acc[mt][2 * pr],     ah[mt], bb[pr][0], bb[pr][1]);
                    mma16816(acc[mt][2 * pr + 1], ah[mt], bb[pr][2], bb[pr][3]);
                }
            }
        }
        __syncthreads();                              // BLO(c) consumed
        if (c < 3) {
            fill_plane(B_LO_OFF, bimg + (c + 1) * 73728 + 36864); CPCOMMIT();
            CPWAIT1();                                // BHI(c+1) done
            __syncthreads();                          // visible to all
        }
        // BLO(c+1) completes during next hi-phase; waited below
        if (c < 3) {
            // ensure BLO(c+1) arrival before its use: wait happens at next
            // iteration boundary via CPWAIT1 ordering (groups FIFO): the next
            // iteration's first CPWAIT is below.
        }
        if (c == 2) { /* last prefetch issued above */ }
        if (c < 3) {
            // before next lo-phase we must wait BLO(c+1): done right after
            // next hi-phase's BHI consume barrier via CPWAIT (placed here for
            // c+1 by the structure: see wait below)
        }
        if (c < 3) { CPWAIT0(); __syncthreads(); }    // BLO(c+1) also ready
    }
    __syncthreads();

    // ---- epilogue: relu+bias, project to 2 outs, reduce --------------------
    {
        const int branch  = cg >> 1;
        const int colbase = branch * 128 + (cg & 1) * 64;
        float y0A[2] = {0, 0}, y1A[2] = {0, 0};
        float y0B[2] = {0, 0}, y1B[2] = {0, 0};
        #pragma unroll
        for (int mt = 0; mt < 2; mt++) {
            #pragma unroll
            for (int nt = 0; nt < 8; nt++) {
                int c0 = colbase + nt * 8 + t * 2;
                float w3a0 = w3a[c0], w3a1 = w3a[c0 + 1];
                float w3b0 = w3b[c0], w3b1 = w3b[c0 + 1];
                float bb0 = b2s[c0], bb1 = b2s[c0 + 1];
                float h0 = fmaxf(acc[mt][nt][0] + bb0, 0.0f);
                float h1 = fmaxf(acc[mt][nt][1] + bb1, 0.0f);
                float h2 = fmaxf(acc[mt][nt][2] + bb0, 0.0f);
                float h3 = fmaxf(acc[mt][nt][3] + bb1, 0.0f);
                y0A[mt] = fmaf(h0, w3a0, fmaf(h1, w3a1, y0A[mt]));
                y1A[mt] = fmaf(h0, w3b0, fmaf(h1, w3b1, y1A[mt]));
                y0B[mt] = fmaf(h2, w3a0, fmaf(h3, w3a1, y0B[mt]));
                y1B[mt] = fmaf(h2, w3b0, fmaf(h3, w3b1, y1B[mt]));
            }
        }
        #pragma unroll
        for (int mt = 0; mt < 2; mt++) {
            #pragma unroll
            for (int msk = 1; msk <= 2; msk <<= 1) {
                y0A[mt] += __shfl_xor_sync(0xFFFFFFFFu, y0A[mt], msk);
                y1A[mt] += __shfl_xor_sync(0xFFFFFFFFu, y1A[mt], msk);
                y0B[mt] += __shfl_xor_sync(0xFFFFFFFFu, y0B[mt], msk);
                y1B[mt] += __shfl_xor_sync(0xFFFFFFFFu, y1B[mt], msk);
            }
        }
        if (t == 0) {
            #pragma unroll
            for (int mt = 0; mt < 2; mt++) {
                int rA = rg * 32 + mt * 16 + g;
                red[cg * 128 + rA]     = make_float2(y0A[mt], y1A[mt]);
                red[cg * 128 + rA + 8] = make_float2(y0B[mt], y1B[mt]);
            }
        }
    }
    __syncthreads();

    if (tid < 128) {
        const int gr = row0 + tid;
        if (gr < Btot) {
            float2 a0 = red[tid],       a1 = red[128 + tid];
            float2 c0 = red[256 + tid], c1 = red[384 + tid];
            float p0 = a0.x + a1.x + b31v[0];
            float p1 = a0.y + a1.y + b31v[1];
            float q0 = c0.x + c1.x + b32v[0];
            float q1 = c0.y + c1.y + b32v[1];
            float s0 = 4.0f / (1.0f + expf(-q0));
            float s1 = 4.0f / (1.0f + expf(-q1));
            float2 z = qp_solve(&xs[tid * 8], p0, p1, s0, s1);
            *(float2*)(out + gr * 2) = z;
        }
    }
}

// ---------------------------------------------------------------- launcher
extern "C" void kernel_launch(void* const* d_in, const int* in_sizes, int n_in,
                              void* d_out, int out_size)
{
    const float* x     = (const float*)d_in[0];
    const float* meanv = (const float*)d_in[1];
    const float* stdv  = (const float*)d_in[2];
    const float* W1    = (const float*)d_in[3];
    const float* b1    = (const float*)d_in[4];
    const float* W21   = (const float*)d_in[5];
    const float* b21   = (const float*)d_in[6];
    const float* W31   = (const float*)d_in[7];
    const float* b31   = (const float*)d_in[8];
    const float* W22   = (const float*)d_in[9];
    const float* b22   = (const float*)d_in[10];
    const float* W32   = (const float*)d_in[11];
    const float* b32   = (const float*)d_in[12];
    float* out = (float*)d_out;

    const int Btot = in_sizes[0] / 8;
    const int grid = (Btot + 127) / 128;

    bnet_prep<<<256, 256>>>(W21, W22);

    cudaFuncSetAttribute(bnet_main, cudaFuncAttributeMaxDynamicSharedMemorySize,
                         SMEM_TOTAL);
    bnet_main<<<grid, NTH, SMEM_TOTAL>>>(x, meanv, stdv, W1, b1,
                                         b21, W31, b31, b22, W32, b32,
                                         out, Btot);
}